// round 13
// baseline (speedup 1.0000x reference)
#include <cuda_runtime.h>
#include <cuda_fp16.h>
#include <cuda_bf16.h>
#include <math.h>
#include <stdint.h>

#define BATCH 64
#define SEQ   1024
#define DIM   200
#define NCLS  31
#define NHEAD 8
#define LN_EPS 1e-5f
#define NPAD  224
#define PHS   208          /* Ph row stride in halves (416 B) */
#define KH    208          /* padded K (halves) for layer GEMMs */

// ---------------- scratch (static device memory; no allocations) ----------------
static __device__ float g_h [BATCH * SEQ * DIM];
static __device__ float g_t [BATCH * SEQ * DIM];
static __device__ float g_c [BATCH * SEQ * DIM];
static __device__ half  g_Ph[(size_t)BATCH * SEQ * PHS];
static __device__ half  g_Whi[4 * NPAD * KH];
static __device__ half  g_Wlo[4 * NPAD * KH];
static __device__ float g_stats[4 * BATCH];
static __device__ float g_acc[4 * BATCH];     // ln accumulators (BSS zero; finalize resets)

extern __shared__ char dyn_smem[];

// ================= helpers =================
__device__ __forceinline__ void mma_f16(float c[4], const uint32_t a[4], const uint32_t b[2]) {
    asm volatile(
        "mma.sync.aligned.m16n8k16.row.col.f32.f16.f16.f32 "
        "{%0,%1,%2,%3}, {%4,%5,%6,%7}, {%8,%9}, {%0,%1,%2,%3};"
        : "+f"(c[0]), "+f"(c[1]), "+f"(c[2]), "+f"(c[3])
        : "r"(a[0]), "r"(a[1]), "r"(a[2]), "r"(a[3]), "r"(b[0]), "r"(b[1]));
}
__device__ __forceinline__ uint32_t smem_u32(const void* p) {
    uint32_t a;
    asm("{ .reg .u64 t; cvta.to.shared.u64 t, %1; cvt.u32.u64 %0, t; }" : "=r"(a) : "l"(p));
    return a;
}
__device__ __forceinline__ void cp16(uint32_t dst, const void* src) {
    asm volatile("cp.async.cg.shared.global [%0], [%1], 16;" :: "r"(dst), "l"(src));
}
#define CP_COMMIT() asm volatile("cp.async.commit_group;" ::: "memory")
#define CP_WAIT0()  asm volatile("cp.async.wait_group 0;" ::: "memory")
__device__ __forceinline__ uint32_t pack_h2(float a, float b) {
    __half2 h = __floats2half2_rn(a, b);
    return *(uint32_t*)&h;
}
__device__ __forceinline__ void ldsm_x4_t(uint32_t& r0, uint32_t& r1, uint32_t& r2, uint32_t& r3,
                                          uint32_t addr) {
    asm volatile("ldmatrix.sync.aligned.m8n8.x4.trans.shared.b16 {%0,%1,%2,%3}, [%4];"
                 : "=r"(r0), "=r"(r1), "=r"(r2), "=r"(r3) : "r"(addr));
}

// ================= small kernels =================
// split weights into fp16 hi/lo planes, transposed [n][k], padded to 224x208
__global__ void wprep_kernel(const float* __restrict__ Wp, const float* __restrict__ Wm,
                             const float* __restrict__ W1, const float* __restrict__ W2,
                             half* __restrict__ Whi, half* __restrict__ Wlo) {
    int i = blockIdx.x * blockDim.x + threadIdx.x;
    if (i >= NPAD * KH) return;
    int n = i / KH, k = i % KH;
    int which = blockIdx.y;
    float v = 0.f;
    if (n < DIM && k < DIM) {
        if (which == 0) v = Wp[k * DIM + n];
        else if (which == 1) {
#pragma unroll
            for (int h = 0; h < NHEAD; h++) v += Wm[(h * DIM + k) * DIM + n];
        } else if (which == 2) v = W1[k * DIM + n];
        else v = W2[k * DIM + n];
    }
    half hv = __float2half_rn(v);
    Whi[which * NPAD * KH + i] = hv;
    Wlo[which * NPAD * KH + i] = __float2half_rn(v - __half2float(hv));
}

__global__ void embed_kernel(const int* __restrict__ x, const float4* __restrict__ emb,
                             const float4* __restrict__ pos, float4* __restrict__ h) {
    int g = blockIdx.x * blockDim.x + threadIdx.x;
    const int Q = DIM / 4;
    if (g >= BATCH * SEQ * Q) return;
    int q = g % Q;
    int r = g / Q;
    int s = r % SEQ;
    int tok = x[r];
    float4 e = emb[(size_t)tok * Q + q];
    float4 p = pos[(size_t)s * Q + q];
    h[g] = make_float4(e.x + p.x, e.y + p.y, e.z + p.z, e.w + p.w);
}

// finalize ln stats; reset accumulators (graph-replay invariant)
__global__ void finalize_kernel(float* __restrict__ acc, float* __restrict__ stats) {
    int b = threadIdx.x;
    if (b < BATCH) {
        float S = acc[2 * b], S2 = acc[2 * b + 1];
        const float n = (float)(SEQ * DIM);
        float mean = S / n;
        float var  = S2 / n - mean * mean;
        stats[2 * b]     = mean;
        stats[2 * b + 1] = rsqrtf(var + LN_EPS);
        acc[2 * b] = 0.f; acc[2 * b + 1] = 0.f;
    }
}

// ====== layer GEMM (fp16 hi/lo mma): Y = op( lnA(X) @ W + bias [+ lnR(res)] ) ======
// TERMS=1: 1-term fp16 (~tf32 precision), single K chunk (208).
// TERMS=3: 3-term hi/lo fp16 (~fp32 precision), 2 K chunks (112, 96).
template <bool RELU, bool ADDRES, bool HOUT, bool ALN, bool RESLN, int TERMS, bool SUMOUT>
__global__ void __launch_bounds__(256) lgemm_kernel(
    const float* __restrict__ X,
    const half* __restrict__ Whi,
    const half* __restrict__ Wlo,
    const float* __restrict__ bias,
    const float* __restrict__ res,
    const float* __restrict__ statsA,
    const float* __restrict__ statsR,
    float* __restrict__ Y,
    half*  __restrict__ Yh,
    float* __restrict__ acc)
{
    // byte row stride of smem planes (16B multiple, conflict-free word phase)
    constexpr int BS = (TERMS == 1) ? 432 : 240;
    constexpr int WS = BS / 4;                       // words per row
    constexpr int AHI = 0;
    constexpr int APL = 128 * BS;                    // one A plane bytes
    constexpr int ALO = (TERMS == 3) ? APL : 0;
    constexpr int BHI = (TERMS == 3) ? 2 * APL : APL;
    constexpr int BPL = 224 * BS;
    constexpr int BLO = BHI + BPL;                   // only used when TERMS==3

    char* sm = dyn_smem;
    const int row0 = blockIdx.x * 128;
    const int b = blockIdx.x >> 3;
    const float4* X4 = (const float4*)(X + (size_t)row0 * DIM);
    const float4* Whi4 = (const float4*)Whi;
    const float4* Wlo4 = (const float4*)Wlo;
    const int tid = threadIdx.x;
    const int warp = tid >> 5, lane = tid & 31;
    const int gid = lane >> 2, tig = lane & 3;
    const int m0 = (warp & 3) * 32;
    const int n0 = (warp >> 2) * 112;

    float mA = 0.f, rA = 1.f;
    if (ALN) { mA = statsA[2 * b]; rA = statsA[2 * b + 1]; }

    float c[2][14][4];
#pragma unroll
    for (int mt = 0; mt < 2; mt++)
#pragma unroll
        for (int nt = 0; nt < 14; nt++)
#pragma unroll
            for (int q = 0; q < 4; q++) c[mt][nt][q] = 0.f;

    const int NCH = (TERMS == 1) ? 1 : 2;
#pragma unroll
    for (int ch = 0; ch < NCH; ch++) {
        const int kh0 = (TERMS == 1) ? 0 : ch * 112;           // chunk start (halves)
        const int kc  = (TERMS == 1) ? 208 : (ch == 0 ? 112 : 96);
        const int G   = kc >> 2;                               // A float4 groups
        const int G2  = kc >> 3;                               // B float4 groups (8 halves)

        // stage A (fp32 -> hi/lo halves), optionally layer-normalized
        for (int idx = tid; idx < 128 * G; idx += 256) {
            int row = idx / G, g = idx - row * G;
            int jg = (kh0 >> 2) + g;
            float4 v = (jg < 50) ? X4[(size_t)row * 50 + jg] : make_float4(0.f, 0.f, 0.f, 0.f);
            if (ALN) {
                v.x = (v.x - mA) * rA; v.y = (v.y - mA) * rA;
                v.z = (v.z - mA) * rA; v.w = (v.w - mA) * rA;
            }
            half hx = __float2half_rn(v.x), hy = __float2half_rn(v.y);
            half hz = __float2half_rn(v.z), hw = __float2half_rn(v.w);
            uint2 hi;
            hi.x = ((uint32_t)__half_as_ushort(hx)) | ((uint32_t)__half_as_ushort(hy) << 16);
            hi.y = ((uint32_t)__half_as_ushort(hz)) | ((uint32_t)__half_as_ushort(hw) << 16);
            *(uint2*)(sm + AHI + row * BS + g * 8) = hi;
            if (TERMS == 3) {
                half lx = __float2half_rn(v.x - __half2float(hx));
                half ly = __float2half_rn(v.y - __half2float(hy));
                half lz = __float2half_rn(v.z - __half2float(hz));
                half lw = __float2half_rn(v.w - __half2float(hw));
                uint2 lo;
                lo.x = ((uint32_t)__half_as_ushort(lx)) | ((uint32_t)__half_as_ushort(ly) << 16);
                lo.y = ((uint32_t)__half_as_ushort(lz)) | ((uint32_t)__half_as_ushort(lw) << 16);
                *(uint2*)(sm + ALO + row * BS + g * 8) = lo;
            }
        }
        // stage B (copy fp16 planes)
        for (int idx = tid; idx < 224 * G2; idx += 256) {
            int row = idx / G2, g = idx - row * G2;
            int jg = (kh0 >> 3) + g;
            *(float4*)(sm + BHI + row * BS + g * 16) = Whi4[(size_t)row * 26 + jg];
            if (TERMS == 3)
                *(float4*)(sm + BLO + row * BS + g * 16) = Wlo4[(size_t)row * 26 + jg];
        }
        __syncthreads();

        const uint32_t* Ah = (const uint32_t*)(sm + AHI);
        const uint32_t* Al = (const uint32_t*)(sm + ALO);
        const uint32_t* Bh = (const uint32_t*)(sm + BHI);
        const uint32_t* Bl = (const uint32_t*)(sm + BLO);
        const int nks = kc >> 4;

        for (int ks = 0; ks < nks; ks++) {
            const int kw = ks * 8 + tig;
            uint32_t ahi[2][4], alo[2][4];
#pragma unroll
            for (int mt = 0; mt < 2; mt++) {
                int r = (m0 + mt * 16 + gid) * WS + kw;
                ahi[mt][0] = Ah[r];           ahi[mt][1] = Ah[r + 8 * WS];
                ahi[mt][2] = Ah[r + 4];       ahi[mt][3] = Ah[r + 8 * WS + 4];
                if (TERMS == 3) {
                    alo[mt][0] = Al[r];       alo[mt][1] = Al[r + 8 * WS];
                    alo[mt][2] = Al[r + 4];   alo[mt][3] = Al[r + 8 * WS + 4];
                }
            }
#pragma unroll
            for (int nt = 0; nt < 14; nt++) {
                int r = (n0 + nt * 8 + gid) * WS + kw;
                uint32_t bhi[2] = { Bh[r], Bh[r + 4] };
                if (TERMS == 3) {
                    uint32_t blo[2] = { Bl[r], Bl[r + 4] };
#pragma unroll
                    for (int mt = 0; mt < 2; mt++) {
                        mma_f16(c[mt][nt], ahi[mt], blo);
                        mma_f16(c[mt][nt], alo[mt], bhi);
                        mma_f16(c[mt][nt], ahi[mt], bhi);
                    }
                } else {
#pragma unroll
                    for (int mt = 0; mt < 2; mt++) mma_f16(c[mt][nt], ahi[mt], bhi);
                }
            }
        }
        __syncthreads();
    }

    float mR = 0.f, rR = 1.f;
    if (RESLN) { mR = statsR[2 * b]; rR = statsR[2 * b + 1]; }

    float* Yb = (!HOUT) ? (Y + (size_t)row0 * DIM) : (float*)0;
    half*  Yhb = HOUT ? (Yh + (size_t)row0 * PHS) : (half*)0;
    const float* Rb = ADDRES ? (res + (size_t)row0 * DIM) : (const float*)0;

    float ssum = 0.f, ssq = 0.f;
#pragma unroll
    for (int mt = 0; mt < 2; mt++) {
        int r0 = m0 + mt * 16 + gid;
#pragma unroll
        for (int nt = 0; nt < 14; nt++) {
            int col = n0 + nt * 8 + 2 * tig;
            if (col < DIM) {
                float bx = bias[col], by = bias[col + 1];
                float v0 = c[mt][nt][0] + bx, v1 = c[mt][nt][1] + by;
                float v2 = c[mt][nt][2] + bx, v3 = c[mt][nt][3] + by;
                if (ADDRES) {
                    float q0 = Rb[(size_t)r0 * DIM + col],       q1 = Rb[(size_t)r0 * DIM + col + 1];
                    float q2 = Rb[(size_t)(r0 + 8) * DIM + col], q3 = Rb[(size_t)(r0 + 8) * DIM + col + 1];
                    if (RESLN) {
                        q0 = (q0 - mR) * rR; q1 = (q1 - mR) * rR;
                        q2 = (q2 - mR) * rR; q3 = (q3 - mR) * rR;
                    }
                    v0 += q0; v1 += q1; v2 += q2; v3 += q3;
                }
                if (RELU) {
                    v0 = fmaxf(v0, 0.f); v1 = fmaxf(v1, 0.f);
                    v2 = fmaxf(v2, 0.f); v3 = fmaxf(v3, 0.f);
                }
                if (SUMOUT) {
                    ssum += (v0 + v1) + (v2 + v3);
                    ssq  += v0 * v0 + v1 * v1 + v2 * v2 + v3 * v3;
                }
                if (HOUT) {
                    *(__half2*)(Yhb + (size_t)r0 * PHS + col)       = __floats2half2_rn(v0, v1);
                    *(__half2*)(Yhb + (size_t)(r0 + 8) * PHS + col) = __floats2half2_rn(v2, v3);
                } else {
                    *(float2*)(Yb + (size_t)r0 * DIM + col)       = make_float2(v0, v1);
                    *(float2*)(Yb + (size_t)(r0 + 8) * DIM + col) = make_float2(v2, v3);
                }
            } else if (HOUT && col < PHS) {
                __half2 z = __floats2half2_rn(0.f, 0.f);
                *(__half2*)(Yhb + (size_t)r0 * PHS + col)       = z;
                *(__half2*)(Yhb + (size_t)(r0 + 8) * PHS + col) = z;
            }
        }
    }
    if (SUMOUT) {
        __shared__ float rbuf[16];
#pragma unroll
        for (int off = 16; off; off >>= 1) {
            ssum += __shfl_xor_sync(0xffffffffu, ssum, off);
            ssq  += __shfl_xor_sync(0xffffffffu, ssq,  off);
        }
        if (lane == 0) { rbuf[warp] = ssum; rbuf[8 + warp] = ssq; }
        __syncthreads();
        if (tid == 0) {
            float S = 0.f, S2 = 0.f;
#pragma unroll
            for (int w = 0; w < 8; w++) { S += rbuf[w]; S2 += rbuf[8 + w]; }
            atomicAdd(acc + 2 * b, S);
            atomicAdd(acc + 2 * b + 1, S2);
        }
    }
}

// ===== fused flash attention: single K/V tile (V == K rows), ldmatrix.trans for V frags =====
// ILP-restructured: scores processes kt-pairs (4 accumulator chains/warp);
// AP loop is kt-outer (25-way independent accumulators).
#define FA_ROWB 432                          /* K-tile row stride bytes (16B-aligned) */
#define FA_BUF  (128 * FA_ROWB)              /* 55296 */
#define FA_SMEM (2 * FA_BUF)                 /* 110592 */

__global__ void __launch_bounds__(256, 1) fattn_kernel(const half* __restrict__ Ph,
                                                       float* __restrict__ C) {
    char* smem = dyn_smem;
    const uint32_t sb = smem_u32(smem);
    const int b = blockIdx.y, s0 = blockIdx.x * 128;
    const int tid = threadIdx.x, warp = tid >> 5, lane = tid & 31;
    const int gid = lane >> 2, tig = lane & 3;
    const int m0 = warp * 16;

    const char* PhB = (const char*)(Ph + (size_t)b * SEQ * PHS);   // row = 416 B

    auto stage = [&](int ch, int buf) {
        uint32_t kbase = sb + buf * FA_BUF;
        const char* ksrc = PhB + (size_t)(ch * 128) * 416;
        for (int i = tid; i < 128 * 26; i += 256) {
            int r = i / 26, c4 = i - r * 26;
            cp16(kbase + r * FA_ROWB + c4 * 16, ksrc + (size_t)r * 416 + c4 * 16);
        }
    };

    // persistent Q fragments (13 k-steps of 16 halves)
    uint32_t qf[13][4];
    {
        const uint32_t* q0 = (const uint32_t*)(PhB + (size_t)(s0 + m0 + gid) * 416);
        const uint32_t* q8 = (const uint32_t*)(PhB + (size_t)(s0 + m0 + gid + 8) * 416);
#pragma unroll
        for (int ks = 0; ks < 13; ks++) {
            qf[ks][0] = q0[ks * 8 + tig];
            qf[ks][1] = q8[ks * 8 + tig];
            qf[ks][2] = q0[ks * 8 + tig + 4];
            qf[ks][3] = q8[ks * 8 + tig + 4];
        }
    }

    // per-lane ldmatrix.x4.trans base: seg0=M1(t+0..7,d0), seg1=M2(t+8..15,d0),
    // seg2=M3(t+0..7,d0+8), seg3=M4(t+8..15,d0+8)
    const uint32_t lbase = (uint32_t)(((lane >> 3) & 1) * 8 * FA_ROWB
                                      + (lane & 7) * FA_ROWB
                                      + ((lane >> 4) & 1) * 16);

    float o[25][4];
#pragma unroll
    for (int nt = 0; nt < 25; nt++)
#pragma unroll
        for (int q = 0; q < 4; q++) o[nt][q] = 0.f;
    float z0 = 0.f, z8 = 0.f;

    stage(0, 0);
    CP_COMMIT();

    for (int ch = 0; ch < 8; ch++) {
        const int buf = ch & 1;
        CP_WAIT0();
        __syncthreads();
        if (ch < 7) { stage(ch + 1, buf ^ 1); CP_COMMIT(); }

        const uint32_t kb = sb + buf * FA_BUF;
        const uint32_t* Kh = (const uint32_t*)(smem + buf * FA_BUF);

        uint32_t afr[8][4];
        const float inv = 0.07071067811865475f;
        // scores: process kt pairs -> 4 independent MMA chains per warp
#pragma unroll
        for (int kp = 0; kp < 4; kp++) {
            float sA[4] = {0.f, 0.f, 0.f, 0.f};   // kt=2kp, rows 0-7
            float sB[4] = {0.f, 0.f, 0.f, 0.f};   // kt=2kp, rows 8-15
            float sC[4] = {0.f, 0.f, 0.f, 0.f};   // kt=2kp+1, rows 0-7
            float sD[4] = {0.f, 0.f, 0.f, 0.f};   // kt=2kp+1, rows 8-15
            const uint32_t* pa = Kh + (kp * 32 + gid) * 108 + tig;
            const uint32_t* pb = pa + 8 * 108;
            const uint32_t* pc = pa + 16 * 108;
            const uint32_t* pd = pa + 24 * 108;
#pragma unroll
            for (int ks = 0; ks < 13; ks++) {
                uint32_t b0[2] = { pa[ks * 8], pa[ks * 8 + 4] };
                mma_f16(sA, qf[ks], b0);
                uint32_t b1[2] = { pb[ks * 8], pb[ks * 8 + 4] };
                mma_f16(sB, qf[ks], b1);
                uint32_t b2[2] = { pc[ks * 8], pc[ks * 8 + 4] };
                mma_f16(sC, qf[ks], b2);
                uint32_t b3[2] = { pd[ks * 8], pd[ks * 8 + 4] };
                mma_f16(sD, qf[ks], b3);
            }
            {
                float e0 = __expf(fmaf(sA[0], inv, -8.f));
                float e1 = __expf(fmaf(sA[1], inv, -8.f));
                float e2 = __expf(fmaf(sA[2], inv, -8.f));
                float e3 = __expf(fmaf(sA[3], inv, -8.f));
                float f0 = __expf(fmaf(sB[0], inv, -8.f));
                float f1 = __expf(fmaf(sB[1], inv, -8.f));
                float f2 = __expf(fmaf(sB[2], inv, -8.f));
                float f3 = __expf(fmaf(sB[3], inv, -8.f));
                z0 += (e0 + e1) + (f0 + f1);
                z8 += (e2 + e3) + (f2 + f3);
                afr[2 * kp][0] = pack_h2(e0, e1);
                afr[2 * kp][1] = pack_h2(e2, e3);
                afr[2 * kp][2] = pack_h2(f0, f1);
                afr[2 * kp][3] = pack_h2(f2, f3);
            }
            {
                float e0 = __expf(fmaf(sC[0], inv, -8.f));
                float e1 = __expf(fmaf(sC[1], inv, -8.f));
                float e2 = __expf(fmaf(sC[2], inv, -8.f));
                float e3 = __expf(fmaf(sC[3], inv, -8.f));
                float f0 = __expf(fmaf(sD[0], inv, -8.f));
                float f1 = __expf(fmaf(sD[1], inv, -8.f));
                float f2 = __expf(fmaf(sD[2], inv, -8.f));
                float f3 = __expf(fmaf(sD[3], inv, -8.f));
                z0 += (e0 + e1) + (f0 + f1);
                z8 += (e2 + e3) + (f2 + f3);
                afr[2 * kp + 1][0] = pack_h2(e0, e1);
                afr[2 * kp + 1][1] = pack_h2(e2, e3);
                afr[2 * kp + 1][2] = pack_h2(f0, f1);
                afr[2 * kp + 1][3] = pack_h2(f2, f3);
            }
        }
        // O += probs @ V, kt-outer: consecutive MMAs hit 25 independent accumulators
#pragma unroll
        for (int kt = 0; kt < 8; kt++) {
            const uint32_t base = kb + lbase + kt * (16 * FA_ROWB);
#pragma unroll
            for (int ntp = 0; ntp < 13; ntp++) {
                uint32_t r0, r1, r2, r3;
                ldsm_x4_t(r0, r1, r2, r3, base + ntp * 32);
                uint32_t bA[2] = { r0, r1 };
                mma_f16(o[2 * ntp], afr[kt], bA);
                if (ntp < 12) {
                    uint32_t bB[2] = { r2, r3 };
                    mma_f16(o[2 * ntp + 1], afr[kt], bB);
                }
            }
        }
    }

    // row-sum reduce across tig lanes; normalize; store
    z0 += __shfl_xor_sync(0xffffffffu, z0, 1);
    z0 += __shfl_xor_sync(0xffffffffu, z0, 2);
    z8 += __shfl_xor_sync(0xffffffffu, z8, 1);
    z8 += __shfl_xor_sync(0xffffffffu, z8, 2);
    float rz0 = 1.f / z0, rz8 = 1.f / z8;

    float* Cb  = C + ((size_t)b * SEQ + s0 + m0 + gid) * DIM;
    float* Cb8 = Cb + 8 * DIM;
#pragma unroll
    for (int nt = 0; nt < 25; nt++) {
        int col = nt * 8 + 2 * tig;
        *(float2*)(Cb  + col) = make_float2(o[nt][0] * rz0, o[nt][1] * rz0);
        *(float2*)(Cb8 + col) = make_float2(o[nt][2] * rz8, o[nt][3] * rz8);
    }
}

// ================= final classifier =================
__global__ void final_kernel(const float* __restrict__ t, const float* __restrict__ stats,
                             const float* __restrict__ Wd, const float* __restrict__ bd,
                             float* __restrict__ out) {
    int b = blockIdx.x;
    int c = threadIdx.x;
    float m = stats[2 * b], rs = stats[2 * b + 1];
    const float* row = t + ((size_t)b * SEQ + (SEQ - 1)) * DIM;
    if (c < NCLS) {
        float acc = bd[c];
        for (int d = 0; d < DIM; d++)
            acc += (row[d] - m) * rs * Wd[d * NCLS + c];
        out[b * NCLS + c] = acc;
    }
}

// ================= host launcher =================
extern "C" void kernel_launch(void* const* d_in, const int* in_sizes, int n_in,
                              void* d_out, int out_size) {
    (void)in_sizes; (void)n_in; (void)out_size;
    const int*   x    = (const int*)  d_in[0];
    const float* emb  = (const float*)d_in[1];
    const float* pos  = (const float*)d_in[2];
    const float* Wp   = (const float*)d_in[3];
    const float* bp   = (const float*)d_in[4];
    const float* Wm   = (const float*)d_in[5];
    const float* bm   = (const float*)d_in[6];
    const float* W1   = (const float*)d_in[7];
    const float* b1   = (const float*)d_in[8];
    const float* W2   = (const float*)d_in[9];
    const float* b2   = (const float*)d_in[10];
    const float* Wd   = (const float*)d_in[11];
    const float* bd   = (const float*)d_in[12];
    float* out = (float*)d_out;

    float *h_, *t_, *c_, *st_, *ac_;
    half *Ph_, *Whi_, *Wlo_;
    cudaGetSymbolAddress((void**)&h_,   g_h);
    cudaGetSymbolAddress((void**)&t_,   g_t);
    cudaGetSymbolAddress((void**)&c_,   g_c);
    cudaGetSymbolAddress((void**)&Ph_,  g_Ph);
    cudaGetSymbolAddress((void**)&Whi_, g_Whi);
    cudaGetSymbolAddress((void**)&Wlo_, g_Wlo);
    cudaGetSymbolAddress((void**)&st_,  g_stats);
    cudaGetSymbolAddress((void**)&ac_,  g_acc);

    const half* WpHi = Whi_;                  const half* WpLo = Wlo_;
    const half* WeHi = Whi_ + 1 * NPAD * KH;  const half* WeLo = Wlo_ + 1 * NPAD * KH;
    const half* W1Hi = Whi_ + 2 * NPAD * KH;  const half* W1Lo = Wlo_ + 2 * NPAD * KH;
    const half* W2Hi = Whi_ + 3 * NPAD * KH;  const half* W2Lo = Wlo_ + 3 * NPAD * KH;
    float* st1 = st_;
    float* st2 = st_ + 2 * BATCH;
    float* ac1 = ac_;
    float* ac2 = ac_ + 2 * BATCH;

    const int SM_LG1 = 128 * 432 + 224 * 432;              // 152064 (TERMS=1)
    const int SM_LG3 = 2 * 128 * 240 + 2 * 224 * 240;      // 168960 (TERMS=3)

    // RELU, ADDRES, HOUT, ALN, RESLN, TERMS, SUMOUT
    auto L_proj0 = lgemm_kernel<false, false, true,  false, false, 1, false>;
    auto L_proj1 = lgemm_kernel<false, false, true,  true,  false, 1, false>;
    auto L_wm0   = lgemm_kernel<false, true,  false, false, false, 3, true >;
    auto L_res3  = lgemm_kernel<false, true,  false, false, true,  3, true >;
    auto L_w1    = lgemm_kernel<true,  false, false, true,  false, 1, false>;
    cudaFuncSetAttribute(L_proj0, cudaFuncAttributeMaxDynamicSharedMemorySize, SM_LG1);
    cudaFuncSetAttribute(L_proj1, cudaFuncAttributeMaxDynamicSharedMemorySize, SM_LG1);
    cudaFuncSetAttribute(L_wm0,   cudaFuncAttributeMaxDynamicSharedMemorySize, SM_LG3);
    cudaFuncSetAttribute(L_res3,  cudaFuncAttributeMaxDynamicSharedMemorySize, SM_LG3);
    cudaFuncSetAttribute(L_w1,    cudaFuncAttributeMaxDynamicSharedMemorySize, SM_LG1);
    cudaFuncSetAttribute(fattn_kernel, cudaFuncAttributeMaxDynamicSharedMemorySize, FA_SMEM);

    const int LGRID = BATCH * SEQ / 128;             // 512
    const int ELT4  = BATCH * SEQ * DIM / 4;

    wprep_kernel<<<dim3((NPAD * KH + 255) / 256, 4), 256>>>(Wp, Wm, W1, W2, Whi_, Wlo_);
    embed_kernel<<<(ELT4 + 255) / 256, 256>>>(x, (const float4*)emb, (const float4*)pos, (float4*)h_);

    for (int st = 0; st < 2; st++) {
        // p = fp16(lnA?(h) @ Wp + bp) -> Ph
        if (st == 0)
            L_proj0<<<LGRID, 256, SM_LG1>>>(h_, WpHi, WpLo, bp, nullptr, nullptr, nullptr, nullptr, Ph_, nullptr);
        else
            L_proj1<<<LGRID, 256, SM_LG1>>>(h_, WpHi, WpLo, bp, nullptr, st2, nullptr, nullptr, Ph_, nullptr);
        // fused attention: c = softmax(P P^T / sqrt(200)) @ P
        fattn_kernel<<<dim3(SEQ / 128, BATCH), 256, FA_SMEM>>>(Ph_, c_);
        // t = c @ WmEff + bm + lnR?(h)   (3-term fp16 trunk, ln-sums fused)
        if (st == 0)
            L_wm0<<<LGRID, 256, SM_LG3>>>(c_, WeHi, WeLo, bm, h_, nullptr, nullptr, t_, nullptr, ac1);
        else
            L_res3<<<LGRID, 256, SM_LG3>>>(c_, WeHi, WeLo, bm, h_, nullptr, st2, t_, nullptr, ac1);
        finalize_kernel<<<1, 64>>>(ac1, st1);
        // ff1 = relu(ln(t) @ W1 + b1)
        L_w1<<<LGRID, 256, SM_LG1>>>(t_, W1Hi, W1Lo, b1, nullptr, st1, nullptr, c_, nullptr, nullptr);
        // t2 = ff1 @ W2 + b2 + ln(t)   (3-term fp16 trunk, ln-sums fused) -> h_
        L_res3<<<LGRID, 256, SM_LG3>>>(c_, W2Hi, W2Lo, b2, t_, nullptr, st1, h_, nullptr, ac2);
        finalize_kernel<<<1, 64>>>(ac2, st2);
    }
    final_kernel<<<BATCH, 32>>>(h_, st2, Wd, bd, out);
}

// round 15
// speedup vs baseline: 1.1452x; 1.1452x over previous
#include <cuda_runtime.h>
#include <cuda_fp16.h>
#include <cuda_bf16.h>
#include <math.h>
#include <stdint.h>

#define BATCH 64
#define SEQ   1024
#define DIM   200
#define NCLS  31
#define NHEAD 8
#define LN_EPS 1e-5f
#define NPAD  224
#define PHS   208          /* Ph row stride in halves (416 B) */
#define KH    208          /* padded K (halves) for layer GEMMs */

// ---------------- scratch (static device memory; no allocations) ----------------
static __device__ float g_h [BATCH * SEQ * DIM];
static __device__ float g_t [BATCH * SEQ * DIM];
static __device__ float g_c [BATCH * SEQ * DIM];
static __device__ half  g_Ph[(size_t)BATCH * SEQ * PHS];
static __device__ half  g_Whi[4 * NPAD * KH];
static __device__ half  g_Wlo[4 * NPAD * KH];
static __device__ float g_stats[4 * BATCH];
static __device__ float g_acc[4 * BATCH];     // ln accumulators (BSS zero; finalize resets)

extern __shared__ char dyn_smem[];

// ================= helpers =================
__device__ __forceinline__ void mma_f16(float c[4], const uint32_t a[4], const uint32_t b[2]) {
    asm volatile(
        "mma.sync.aligned.m16n8k16.row.col.f32.f16.f16.f32 "
        "{%0,%1,%2,%3}, {%4,%5,%6,%7}, {%8,%9}, {%0,%1,%2,%3};"
        : "+f"(c[0]), "+f"(c[1]), "+f"(c[2]), "+f"(c[3])
        : "r"(a[0]), "r"(a[1]), "r"(a[2]), "r"(a[3]), "r"(b[0]), "r"(b[1]));
}
__device__ __forceinline__ uint32_t smem_u32(const void* p) {
    uint32_t a;
    asm("{ .reg .u64 t; cvta.to.shared.u64 t, %1; cvt.u32.u64 %0, t; }" : "=r"(a) : "l"(p));
    return a;
}
__device__ __forceinline__ void cp16(uint32_t dst, const void* src) {
    asm volatile("cp.async.cg.shared.global [%0], [%1], 16;" :: "r"(dst), "l"(src));
}
#define CP_COMMIT() asm volatile("cp.async.commit_group;" ::: "memory")
#define CP_WAIT0()  asm volatile("cp.async.wait_group 0;" ::: "memory")
__device__ __forceinline__ uint32_t pack_h2(float a, float b) {
    __half2 h = __floats2half2_rn(a, b);
    return *(uint32_t*)&h;
}
__device__ __forceinline__ void ldsm_x4_t(uint32_t& r0, uint32_t& r1, uint32_t& r2, uint32_t& r3,
                                          uint32_t addr) {
    asm volatile("ldmatrix.sync.aligned.m8n8.x4.trans.shared.b16 {%0,%1,%2,%3}, [%4];"
                 : "=r"(r0), "=r"(r1), "=r"(r2), "=r"(r3) : "r"(addr));
}

// ================= small kernels =================
// split weights into fp16 hi/lo planes, transposed [n][k], padded to 224x208
__global__ void wprep_kernel(const float* __restrict__ Wp, const float* __restrict__ Wm,
                             const float* __restrict__ W1, const float* __restrict__ W2,
                             half* __restrict__ Whi, half* __restrict__ Wlo) {
    int i = blockIdx.x * blockDim.x + threadIdx.x;
    if (i >= NPAD * KH) return;
    int n = i / KH, k = i % KH;
    int which = blockIdx.y;
    float v = 0.f;
    if (n < DIM && k < DIM) {
        if (which == 0) v = Wp[k * DIM + n];
        else if (which == 1) {
#pragma unroll
            for (int h = 0; h < NHEAD; h++) v += Wm[(h * DIM + k) * DIM + n];
        } else if (which == 2) v = W1[k * DIM + n];
        else v = W2[k * DIM + n];
    }
    half hv = __float2half_rn(v);
    Whi[which * NPAD * KH + i] = hv;
    Wlo[which * NPAD * KH + i] = __float2half_rn(v - __half2float(hv));
}

__global__ void embed_kernel(const int* __restrict__ x, const float4* __restrict__ emb,
                             const float4* __restrict__ pos, float4* __restrict__ h) {
    int g = blockIdx.x * blockDim.x + threadIdx.x;
    const int Q = DIM / 4;
    if (g >= BATCH * SEQ * Q) return;
    int q = g % Q;
    int r = g / Q;
    int s = r % SEQ;
    int tok = x[r];
    float4 e = emb[(size_t)tok * Q + q];
    float4 p = pos[(size_t)s * Q + q];
    h[g] = make_float4(e.x + p.x, e.y + p.y, e.z + p.z, e.w + p.w);
}

// finalize ln stats; reset accumulators (graph-replay invariant)
__global__ void finalize_kernel(float* __restrict__ acc, float* __restrict__ stats) {
    int b = threadIdx.x;
    if (b < BATCH) {
        float S = acc[2 * b], S2 = acc[2 * b + 1];
        const float n = (float)(SEQ * DIM);
        float mean = S / n;
        float var  = S2 / n - mean * mean;
        stats[2 * b]     = mean;
        stats[2 * b + 1] = rsqrtf(var + LN_EPS);
        acc[2 * b] = 0.f; acc[2 * b + 1] = 0.f;
    }
}

// ====== layer GEMM (fp16 hi/lo mma): Y = op( lnA(X) @ W + bias [+ lnR(res)] ) ======
// 512 threads, 16 warps, warp tile 32(M) x 56(N). CTA tile 128 x 224.
// TERMS=1: 1-term fp16 (~tf32 precision), single K chunk (208).
// TERMS=3: 3-term hi/lo fp16 (~fp32 precision), 2 K chunks (112, 96).
template <bool RELU, bool ADDRES, bool HOUT, bool ALN, bool RESLN, int TERMS, bool SUMOUT>
__global__ void __launch_bounds__(512) lgemm_kernel(
    const float* __restrict__ X,
    const half* __restrict__ Whi,
    const half* __restrict__ Wlo,
    const float* __restrict__ bias,
    const float* __restrict__ res,
    const float* __restrict__ statsA,
    const float* __restrict__ statsR,
    float* __restrict__ Y,
    half*  __restrict__ Yh,
    float* __restrict__ acc)
{
    // byte row stride of smem planes (16B multiple, conflict-free word phase)
    constexpr int BS = (TERMS == 1) ? 432 : 240;
    constexpr int WS = BS / 4;                       // words per row
    constexpr int AHI = 0;
    constexpr int APL = 128 * BS;                    // one A plane bytes
    constexpr int ALO = (TERMS == 3) ? APL : 0;
    constexpr int BHI = (TERMS == 3) ? 2 * APL : APL;
    constexpr int BPL = 224 * BS;
    constexpr int BLO = BHI + BPL;                   // only used when TERMS==3

    char* sm = dyn_smem;
    const int row0 = blockIdx.x * 128;
    const int b = blockIdx.x >> 3;
    const float4* X4 = (const float4*)(X + (size_t)row0 * DIM);
    const float4* Whi4 = (const float4*)Whi;
    const float4* Wlo4 = (const float4*)Wlo;
    const int tid = threadIdx.x;
    const int warp = tid >> 5, lane = tid & 31;
    const int gid = lane >> 2, tig = lane & 3;
    const int m0 = (warp & 3) * 32;
    const int n0 = (warp >> 2) * 56;

    float mA = 0.f, rA = 1.f;
    if (ALN) { mA = statsA[2 * b]; rA = statsA[2 * b + 1]; }

    float c[2][7][4];
#pragma unroll
    for (int mt = 0; mt < 2; mt++)
#pragma unroll
        for (int nt = 0; nt < 7; nt++)
#pragma unroll
            for (int q = 0; q < 4; q++) c[mt][nt][q] = 0.f;

    const int NCH = (TERMS == 1) ? 1 : 2;
#pragma unroll
    for (int ch = 0; ch < NCH; ch++) {
        const int kh0 = (TERMS == 1) ? 0 : ch * 112;           // chunk start (halves)
        const int kc  = (TERMS == 1) ? 208 : (ch == 0 ? 112 : 96);
        const int G   = kc >> 2;                               // A float4 groups
        const int G2  = kc >> 3;                               // B float4 groups (8 halves)

        // stage A (fp32 -> hi/lo halves), optionally layer-normalized
        for (int idx = tid; idx < 128 * G; idx += 512) {
            int row = idx / G, g = idx - row * G;
            int jg = (kh0 >> 2) + g;
            float4 v = (jg < 50) ? X4[(size_t)row * 50 + jg] : make_float4(0.f, 0.f, 0.f, 0.f);
            if (ALN) {
                v.x = (v.x - mA) * rA; v.y = (v.y - mA) * rA;
                v.z = (v.z - mA) * rA; v.w = (v.w - mA) * rA;
            }
            half hx = __float2half_rn(v.x), hy = __float2half_rn(v.y);
            half hz = __float2half_rn(v.z), hw = __float2half_rn(v.w);
            uint2 hi;
            hi.x = ((uint32_t)__half_as_ushort(hx)) | ((uint32_t)__half_as_ushort(hy) << 16);
            hi.y = ((uint32_t)__half_as_ushort(hz)) | ((uint32_t)__half_as_ushort(hw) << 16);
            *(uint2*)(sm + AHI + row * BS + g * 8) = hi;
            if (TERMS == 3) {
                half lx = __float2half_rn(v.x - __half2float(hx));
                half ly = __float2half_rn(v.y - __half2float(hy));
                half lz = __float2half_rn(v.z - __half2float(hz));
                half lw = __float2half_rn(v.w - __half2float(hw));
                uint2 lo;
                lo.x = ((uint32_t)__half_as_ushort(lx)) | ((uint32_t)__half_as_ushort(ly) << 16);
                lo.y = ((uint32_t)__half_as_ushort(lz)) | ((uint32_t)__half_as_ushort(lw) << 16);
                *(uint2*)(sm + ALO + row * BS + g * 8) = lo;
            }
        }
        // stage B (copy fp16 planes)
        for (int idx = tid; idx < 224 * G2; idx += 512) {
            int row = idx / G2, g = idx - row * G2;
            int jg = (kh0 >> 3) + g;
            *(float4*)(sm + BHI + row * BS + g * 16) = Whi4[(size_t)row * 26 + jg];
            if (TERMS == 3)
                *(float4*)(sm + BLO + row * BS + g * 16) = Wlo4[(size_t)row * 26 + jg];
        }
        __syncthreads();

        const uint32_t* Ah = (const uint32_t*)(sm + AHI);
        const uint32_t* Al = (const uint32_t*)(sm + ALO);
        const uint32_t* Bh = (const uint32_t*)(sm + BHI);
        const uint32_t* Bl = (const uint32_t*)(sm + BLO);
        const int nks = kc >> 4;

        for (int ks = 0; ks < nks; ks++) {
            const int kw = ks * 8 + tig;
            uint32_t ahi[2][4], alo[2][4];
#pragma unroll
            for (int mt = 0; mt < 2; mt++) {
                int r = (m0 + mt * 16 + gid) * WS + kw;
                ahi[mt][0] = Ah[r];           ahi[mt][1] = Ah[r + 8 * WS];
                ahi[mt][2] = Ah[r + 4];       ahi[mt][3] = Ah[r + 8 * WS + 4];
                if (TERMS == 3) {
                    alo[mt][0] = Al[r];       alo[mt][1] = Al[r + 8 * WS];
                    alo[mt][2] = Al[r + 4];   alo[mt][3] = Al[r + 8 * WS + 4];
                }
            }
#pragma unroll
            for (int nt = 0; nt < 7; nt++) {
                int r = (n0 + nt * 8 + gid) * WS + kw;
                uint32_t bhi[2] = { Bh[r], Bh[r + 4] };
                if (TERMS == 3) {
                    uint32_t blo[2] = { Bl[r], Bl[r + 4] };
#pragma unroll
                    for (int mt = 0; mt < 2; mt++) {
                        mma_f16(c[mt][nt], ahi[mt], blo);
                        mma_f16(c[mt][nt], alo[mt], bhi);
                        mma_f16(c[mt][nt], ahi[mt], bhi);
                    }
                } else {
#pragma unroll
                    for (int mt = 0; mt < 2; mt++) mma_f16(c[mt][nt], ahi[mt], bhi);
                }
            }
        }
        __syncthreads();
    }

    float mR = 0.f, rR = 1.f;
    if (RESLN) { mR = statsR[2 * b]; rR = statsR[2 * b + 1]; }

    float* Yb = (!HOUT) ? (Y + (size_t)row0 * DIM) : (float*)0;
    half*  Yhb = HOUT ? (Yh + (size_t)row0 * PHS) : (half*)0;
    const float* Rb = ADDRES ? (res + (size_t)row0 * DIM) : (const float*)0;

    float ssum = 0.f, ssq = 0.f;
#pragma unroll
    for (int mt = 0; mt < 2; mt++) {
        int r0 = m0 + mt * 16 + gid;
#pragma unroll
        for (int nt = 0; nt < 7; nt++) {
            int col = n0 + nt * 8 + 2 * tig;
            if (col < DIM) {
                float bx = bias[col], by = bias[col + 1];
                float v0 = c[mt][nt][0] + bx, v1 = c[mt][nt][1] + by;
                float v2 = c[mt][nt][2] + bx, v3 = c[mt][nt][3] + by;
                if (ADDRES) {
                    float q0 = Rb[(size_t)r0 * DIM + col],       q1 = Rb[(size_t)r0 * DIM + col + 1];
                    float q2 = Rb[(size_t)(r0 + 8) * DIM + col], q3 = Rb[(size_t)(r0 + 8) * DIM + col + 1];
                    if (RESLN) {
                        q0 = (q0 - mR) * rR; q1 = (q1 - mR) * rR;
                        q2 = (q2 - mR) * rR; q3 = (q3 - mR) * rR;
                    }
                    v0 += q0; v1 += q1; v2 += q2; v3 += q3;
                }
                if (RELU) {
                    v0 = fmaxf(v0, 0.f); v1 = fmaxf(v1, 0.f);
                    v2 = fmaxf(v2, 0.f); v3 = fmaxf(v3, 0.f);
                }
                if (SUMOUT) {
                    ssum += (v0 + v1) + (v2 + v3);
                    ssq  += v0 * v0 + v1 * v1 + v2 * v2 + v3 * v3;
                }
                if (HOUT) {
                    *(__half2*)(Yhb + (size_t)r0 * PHS + col)       = __floats2half2_rn(v0, v1);
                    *(__half2*)(Yhb + (size_t)(r0 + 8) * PHS + col) = __floats2half2_rn(v2, v3);
                } else {
                    *(float2*)(Yb + (size_t)r0 * DIM + col)       = make_float2(v0, v1);
                    *(float2*)(Yb + (size_t)(r0 + 8) * DIM + col) = make_float2(v2, v3);
                }
            } else if (HOUT && col < PHS) {
                __half2 z = __floats2half2_rn(0.f, 0.f);
                *(__half2*)(Yhb + (size_t)r0 * PHS + col)       = z;
                *(__half2*)(Yhb + (size_t)(r0 + 8) * PHS + col) = z;
            }
        }
    }
    if (SUMOUT) {
        __shared__ float rbuf[32];
#pragma unroll
        for (int off = 16; off; off >>= 1) {
            ssum += __shfl_xor_sync(0xffffffffu, ssum, off);
            ssq  += __shfl_xor_sync(0xffffffffu, ssq,  off);
        }
        if (lane == 0) { rbuf[warp] = ssum; rbuf[16 + warp] = ssq; }
        __syncthreads();
        if (tid == 0) {
            float S = 0.f, S2 = 0.f;
#pragma unroll
            for (int w = 0; w < 16; w++) { S += rbuf[w]; S2 += rbuf[16 + w]; }
            atomicAdd(acc + 2 * b, S);
            atomicAdd(acc + 2 * b + 1, S2);
        }
    }
}

// ===== fused flash attention (R12 version): single K/V tile, ldmatrix.trans V frags =====
#define FA_ROWB 432                          /* K-tile row stride bytes (16B-aligned) */
#define FA_BUF  (128 * FA_ROWB)              /* 55296 */
#define FA_SMEM (2 * FA_BUF)                 /* 110592 */

__global__ void __launch_bounds__(256, 1) fattn_kernel(const half* __restrict__ Ph,
                                                       float* __restrict__ C) {
    char* smem = dyn_smem;
    const uint32_t sb = smem_u32(smem);
    const int b = blockIdx.y, s0 = blockIdx.x * 128;
    const int tid = threadIdx.x, warp = tid >> 5, lane = tid & 31;
    const int gid = lane >> 2, tig = lane & 3;
    const int m0 = warp * 16;

    const char* PhB = (const char*)(Ph + (size_t)b * SEQ * PHS);   // row = 416 B

    auto stage = [&](int ch, int buf) {
        uint32_t kbase = sb + buf * FA_BUF;
        const char* ksrc = PhB + (size_t)(ch * 128) * 416;
        for (int i = tid; i < 128 * 26; i += 256) {
            int r = i / 26, c4 = i - r * 26;
            cp16(kbase + r * FA_ROWB + c4 * 16, ksrc + (size_t)r * 416 + c4 * 16);
        }
    };

    // persistent Q fragments (13 k-steps of 16 halves)
    uint32_t qf[13][4];
    {
        const uint32_t* q0 = (const uint32_t*)(PhB + (size_t)(s0 + m0 + gid) * 416);
        const uint32_t* q8 = (const uint32_t*)(PhB + (size_t)(s0 + m0 + gid + 8) * 416);
#pragma unroll
        for (int ks = 0; ks < 13; ks++) {
            qf[ks][0] = q0[ks * 8 + tig];
            qf[ks][1] = q8[ks * 8 + tig];
            qf[ks][2] = q0[ks * 8 + tig + 4];
            qf[ks][3] = q8[ks * 8 + tig + 4];
        }
    }

    // per-lane ldmatrix.x4.trans base: seg0=M1(t+0..7,d0), seg1=M2(t+8..15,d0),
    // seg2=M3(t+0..7,d0+8), seg3=M4(t+8..15,d0+8)
    const uint32_t lbase = (uint32_t)(((lane >> 3) & 1) * 8 * FA_ROWB
                                      + (lane & 7) * FA_ROWB
                                      + ((lane >> 4) & 1) * 16);

    float o[25][4];
#pragma unroll
    for (int nt = 0; nt < 25; nt++)
#pragma unroll
        for (int q = 0; q < 4; q++) o[nt][q] = 0.f;
    float z0 = 0.f, z8 = 0.f;

    stage(0, 0);
    CP_COMMIT();

    for (int ch = 0; ch < 8; ch++) {
        const int buf = ch & 1;
        CP_WAIT0();
        __syncthreads();
        if (ch < 7) { stage(ch + 1, buf ^ 1); CP_COMMIT(); }

        const uint32_t kb = sb + buf * FA_BUF;
        const uint32_t* Kh = (const uint32_t*)(smem + buf * FA_BUF);

        uint32_t afr[8][4];
        const float inv = 0.07071067811865475f;
#pragma unroll
        for (int kt = 0; kt < 8; kt++) {
            float sa[4] = {0.f, 0.f, 0.f, 0.f};
            float sc[4] = {0.f, 0.f, 0.f, 0.f};
            const uint32_t* k0p = Kh + (kt * 16 + gid) * 108 + tig;
            const uint32_t* k1p = k0p + 8 * 108;
#pragma unroll
            for (int ks = 0; ks < 13; ks++) {
                uint32_t b0[2] = { k0p[ks * 8], k0p[ks * 8 + 4] };
                mma_f16(sa, qf[ks], b0);
                uint32_t b1[2] = { k1p[ks * 8], k1p[ks * 8 + 4] };
                mma_f16(sc, qf[ks], b1);
            }
            float e0 = __expf(fmaf(sa[0], inv, -8.f));
            float e1 = __expf(fmaf(sa[1], inv, -8.f));
            float e2 = __expf(fmaf(sa[2], inv, -8.f));
            float e3 = __expf(fmaf(sa[3], inv, -8.f));
            float f0 = __expf(fmaf(sc[0], inv, -8.f));
            float f1 = __expf(fmaf(sc[1], inv, -8.f));
            float f2 = __expf(fmaf(sc[2], inv, -8.f));
            float f3 = __expf(fmaf(sc[3], inv, -8.f));
            z0 += (e0 + e1) + (f0 + f1);
            z8 += (e2 + e3) + (f2 + f3);
            afr[kt][0] = pack_h2(e0, e1);
            afr[kt][1] = pack_h2(e2, e3);
            afr[kt][2] = pack_h2(f0, f1);
            afr[kt][3] = pack_h2(f2, f3);
        }
        // O += probs @ V, V fragments via ldmatrix.trans from the SAME K tile
#pragma unroll
        for (int ntp = 0; ntp < 13; ntp++) {
#pragma unroll
            for (int kt = 0; kt < 8; kt++) {
                uint32_t r0, r1, r2, r3;
                ldsm_x4_t(r0, r1, r2, r3, kb + lbase + kt * (16 * FA_ROWB) + ntp * 32);
                uint32_t bA[2] = { r0, r1 };
                mma_f16(o[2 * ntp], afr[kt], bA);
                if (ntp < 12) {
                    uint32_t bB[2] = { r2, r3 };
                    mma_f16(o[2 * ntp + 1], afr[kt], bB);
                }
            }
        }
    }

    // row-sum reduce across tig lanes; normalize; store
    z0 += __shfl_xor_sync(0xffffffffu, z0, 1);
    z0 += __shfl_xor_sync(0xffffffffu, z0, 2);
    z8 += __shfl_xor_sync(0xffffffffu, z8, 1);
    z8 += __shfl_xor_sync(0xffffffffu, z8, 2);
    float rz0 = 1.f / z0, rz8 = 1.f / z8;

    float* Cb  = C + ((size_t)b * SEQ + s0 + m0 + gid) * DIM;
    float* Cb8 = Cb + 8 * DIM;
#pragma unroll
    for (int nt = 0; nt < 25; nt++) {
        int col = nt * 8 + 2 * tig;
        *(float2*)(Cb  + col) = make_float2(o[nt][0] * rz0, o[nt][1] * rz0);
        *(float2*)(Cb8 + col) = make_float2(o[nt][2] * rz8, o[nt][3] * rz8);
    }
}

// ================= final classifier =================
__global__ void final_kernel(const float* __restrict__ t, const float* __restrict__ stats,
                             const float* __restrict__ Wd, const float* __restrict__ bd,
                             float* __restrict__ out) {
    int b = blockIdx.x;
    int c = threadIdx.x;
    float m = stats[2 * b], rs = stats[2 * b + 1];
    const float* row = t + ((size_t)b * SEQ + (SEQ - 1)) * DIM;
    if (c < NCLS) {
        float acc = bd[c];
        for (int d = 0; d < DIM; d++)
            acc += (row[d] - m) * rs * Wd[d * NCLS + c];
        out[b * NCLS + c] = acc;
    }
}

// ================= host launcher =================
extern "C" void kernel_launch(void* const* d_in, const int* in_sizes, int n_in,
                              void* d_out, int out_size) {
    (void)in_sizes; (void)n_in; (void)out_size;
    const int*   x    = (const int*)  d_in[0];
    const float* emb  = (const float*)d_in[1];
    const float* pos  = (const float*)d_in[2];
    const float* Wp   = (const float*)d_in[3];
    const float* bp   = (const float*)d_in[4];
    const float* Wm   = (const float*)d_in[5];
    const float* bm   = (const float*)d_in[6];
    const float* W1   = (const float*)d_in[7];
    const float* b1   = (const float*)d_in[8];
    const float* W2   = (const float*)d_in[9];
    const float* b2   = (const float*)d_in[10];
    const float* Wd   = (const float*)d_in[11];
    const float* bd   = (const float*)d_in[12];
    float* out = (float*)d_out;

    float *h_, *t_, *c_, *st_, *ac_;
    half *Ph_, *Whi_, *Wlo_;
    cudaGetSymbolAddress((void**)&h_,   g_h);
    cudaGetSymbolAddress((void**)&t_,   g_t);
    cudaGetSymbolAddress((void**)&c_,   g_c);
    cudaGetSymbolAddress((void**)&Ph_,  g_Ph);
    cudaGetSymbolAddress((void**)&Whi_, g_Whi);
    cudaGetSymbolAddress((void**)&Wlo_, g_Wlo);
    cudaGetSymbolAddress((void**)&st_,  g_stats);
    cudaGetSymbolAddress((void**)&ac_,  g_acc);

    const half* WpHi = Whi_;                  const half* WpLo = Wlo_;
    const half* WeHi = Whi_ + 1 * NPAD * KH;  const half* WeLo = Wlo_ + 1 * NPAD * KH;
    const half* W1Hi = Whi_ + 2 * NPAD * KH;  const half* W1Lo = Wlo_ + 2 * NPAD * KH;
    const half* W2Hi = Whi_ + 3 * NPAD * KH;  const half* W2Lo = Wlo_ + 3 * NPAD * KH;
    float* st1 = st_;
    float* st2 = st_ + 2 * BATCH;
    float* ac1 = ac_;
    float* ac2 = ac_ + 2 * BATCH;

    const int SM_LG1 = 128 * 432 + 224 * 432;              // 152064 (TERMS=1)
    const int SM_LG3 = 2 * 128 * 240 + 2 * 224 * 240;      // 168960 (TERMS=3)

    // RELU, ADDRES, HOUT, ALN, RESLN, TERMS, SUMOUT
    auto L_proj0 = lgemm_kernel<false, false, true,  false, false, 1, false>;
    auto L_proj1 = lgemm_kernel<false, false, true,  true,  false, 1, false>;
    auto L_wm0   = lgemm_kernel<false, true,  false, false, false, 3, true >;
    auto L_res3  = lgemm_kernel<false, true,  false, false, true,  3, true >;
    auto L_w1    = lgemm_kernel<true,  false, false, true,  false, 1, false>;
    cudaFuncSetAttribute(L_proj0, cudaFuncAttributeMaxDynamicSharedMemorySize, SM_LG1);
    cudaFuncSetAttribute(L_proj1, cudaFuncAttributeMaxDynamicSharedMemorySize, SM_LG1);
    cudaFuncSetAttribute(L_wm0,   cudaFuncAttributeMaxDynamicSharedMemorySize, SM_LG3);
    cudaFuncSetAttribute(L_res3,  cudaFuncAttributeMaxDynamicSharedMemorySize, SM_LG3);
    cudaFuncSetAttribute(L_w1,    cudaFuncAttributeMaxDynamicSharedMemorySize, SM_LG1);
    cudaFuncSetAttribute(fattn_kernel, cudaFuncAttributeMaxDynamicSharedMemorySize, FA_SMEM);

    const int LGRID = BATCH * SEQ / 128;             // 512
    const int ELT4  = BATCH * SEQ * DIM / 4;

    wprep_kernel<<<dim3((NPAD * KH + 255) / 256, 4), 256>>>(Wp, Wm, W1, W2, Whi_, Wlo_);
    embed_kernel<<<(ELT4 + 255) / 256, 256>>>(x, (const float4*)emb, (const float4*)pos, (float4*)h_);

    for (int st = 0; st < 2; st++) {
        // p = fp16(lnA?(h) @ Wp + bp) -> Ph
        if (st == 0)
            L_proj0<<<LGRID, 512, SM_LG1>>>(h_, WpHi, WpLo, bp, nullptr, nullptr, nullptr, nullptr, Ph_, nullptr);
        else
            L_proj1<<<LGRID, 512, SM_LG1>>>(h_, WpHi, WpLo, bp, nullptr, st2, nullptr, nullptr, Ph_, nullptr);
        // fused attention: c = softmax(P P^T / sqrt(200)) @ P
        fattn_kernel<<<dim3(SEQ / 128, BATCH), 256, FA_SMEM>>>(Ph_, c_);
        // t = c @ WmEff + bm + lnR?(h)   (3-term fp16 trunk, ln-sums fused)
        if (st == 0)
            L_wm0<<<LGRID, 512, SM_LG3>>>(c_, WeHi, WeLo, bm, h_, nullptr, nullptr, t_, nullptr, ac1);
        else
            L_res3<<<LGRID, 512, SM_LG3>>>(c_, WeHi, WeLo, bm, h_, nullptr, st2, t_, nullptr, ac1);
        finalize_kernel<<<1, 64>>>(ac1, st1);
        // ff1 = relu(ln(t) @ W1 + b1)
        L_w1<<<LGRID, 512, SM_LG1>>>(t_, W1Hi, W1Lo, b1, nullptr, st1, nullptr, c_, nullptr, nullptr);
        // t2 = ff1 @ W2 + b2 + ln(t)   (3-term fp16 trunk, ln-sums fused) -> h_
        L_res3<<<LGRID, 512, SM_LG3>>>(c_, W2Hi, W2Lo, b2, t_, nullptr, st1, h_, nullptr, ac2);
        finalize_kernel<<<1, 64>>>(ac2, st2);
    }
    final_kernel<<<BATCH, 32>>>(h_, st2, Wd, bd, out);
}

// round 16
// speedup vs baseline: 1.2222x; 1.0673x over previous
#include <cuda_runtime.h>
#include <cuda_fp16.h>
#include <cuda_bf16.h>
#include <math.h>
#include <stdint.h>

#define BATCH 64
#define SEQ   1024
#define DIM   200
#define NCLS  31
#define NHEAD 8
#define LN_EPS 1e-5f
#define NPAD  224
#define PHS   208          /* Ph row stride in halves (416 B) */
#define KH    208          /* padded K (halves) for layer GEMMs */

// ---------------- scratch (static device memory; no allocations) ----------------
static __device__ float g_h [BATCH * SEQ * DIM];
static __device__ float g_t [BATCH * SEQ * DIM];
static __device__ float g_c [BATCH * SEQ * DIM];
static __device__ half  g_Ph[(size_t)BATCH * SEQ * PHS];
static __device__ half  g_Whi[4 * NPAD * KH];
static __device__ half  g_Wlo[4 * NPAD * KH];
static __device__ float g_stats[4 * BATCH];
static __device__ float g_acc[4 * BATCH];     // ln accumulators (BSS zero; finalize resets)

extern __shared__ char dyn_smem[];

// ================= helpers =================
__device__ __forceinline__ void mma_f16(float c[4], const uint32_t a[4], const uint32_t b[2]) {
    asm volatile(
        "mma.sync.aligned.m16n8k16.row.col.f32.f16.f16.f32 "
        "{%0,%1,%2,%3}, {%4,%5,%6,%7}, {%8,%9}, {%0,%1,%2,%3};"
        : "+f"(c[0]), "+f"(c[1]), "+f"(c[2]), "+f"(c[3])
        : "r"(a[0]), "r"(a[1]), "r"(a[2]), "r"(a[3]), "r"(b[0]), "r"(b[1]));
}
__device__ __forceinline__ uint32_t smem_u32(const void* p) {
    uint32_t a;
    asm("{ .reg .u64 t; cvta.to.shared.u64 t, %1; cvt.u32.u64 %0, t; }" : "=r"(a) : "l"(p));
    return a;
}
__device__ __forceinline__ void cp16(uint32_t dst, const void* src) {
    asm volatile("cp.async.cg.shared.global [%0], [%1], 16;" :: "r"(dst), "l"(src));
}
#define CP_COMMIT() asm volatile("cp.async.commit_group;" ::: "memory")
#define CP_WAIT0()  asm volatile("cp.async.wait_group 0;" ::: "memory")
__device__ __forceinline__ uint32_t pack_h2(float a, float b) {
    __half2 h = __floats2half2_rn(a, b);
    return *(uint32_t*)&h;
}
__device__ __forceinline__ void ldsm_x4_t(uint32_t& r0, uint32_t& r1, uint32_t& r2, uint32_t& r3,
                                          uint32_t addr) {
    asm volatile("ldmatrix.sync.aligned.m8n8.x4.trans.shared.b16 {%0,%1,%2,%3}, [%4];"
                 : "=r"(r0), "=r"(r1), "=r"(r2), "=r"(r3) : "r"(addr));
}

// ================= small kernels =================
// split weights into fp16 hi/lo planes, transposed [n][k], padded to 224x208
__global__ void wprep_kernel(const float* __restrict__ Wp, const float* __restrict__ Wm,
                             const float* __restrict__ W1, const float* __restrict__ W2,
                             half* __restrict__ Whi, half* __restrict__ Wlo) {
    int i = blockIdx.x * blockDim.x + threadIdx.x;
    if (i >= NPAD * KH) return;
    int n = i / KH, k = i % KH;
    int which = blockIdx.y;
    float v = 0.f;
    if (n < DIM && k < DIM) {
        if (which == 0) v = Wp[k * DIM + n];
        else if (which == 1) {
#pragma unroll
            for (int h = 0; h < NHEAD; h++) v += Wm[(h * DIM + k) * DIM + n];
        } else if (which == 2) v = W1[k * DIM + n];
        else v = W2[k * DIM + n];
    }
    half hv = __float2half_rn(v);
    Whi[which * NPAD * KH + i] = hv;
    Wlo[which * NPAD * KH + i] = __float2half_rn(v - __half2float(hv));
}

__global__ void embed_kernel(const int* __restrict__ x, const float4* __restrict__ emb,
                             const float4* __restrict__ pos, float4* __restrict__ h) {
    int g = blockIdx.x * blockDim.x + threadIdx.x;
    const int Q = DIM / 4;
    if (g >= BATCH * SEQ * Q) return;
    int q = g % Q;
    int r = g / Q;
    int s = r % SEQ;
    int tok = x[r];
    float4 e = emb[(size_t)tok * Q + q];
    float4 p = pos[(size_t)s * Q + q];
    h[g] = make_float4(e.x + p.x, e.y + p.y, e.z + p.z, e.w + p.w);
}

// finalize ln stats; reset accumulators (graph-replay invariant)
__global__ void finalize_kernel(float* __restrict__ acc, float* __restrict__ stats) {
    int b = threadIdx.x;
    if (b < BATCH) {
        float S = acc[2 * b], S2 = acc[2 * b + 1];
        const float n = (float)(SEQ * DIM);
        float mean = S / n;
        float var  = S2 / n - mean * mean;
        stats[2 * b]     = mean;
        stats[2 * b + 1] = rsqrtf(var + LN_EPS);
        acc[2 * b] = 0.f; acc[2 * b + 1] = 0.f;
    }
}

// ====== layer GEMM (fp16 hi/lo mma): Y = op( lnA(X) @ W + bias [+ lnR(res)] ) ======
// 512 threads, 16 warps, warp tile 32(M) x 56(N). CTA tile 128 x 224.
template <bool RELU, bool ADDRES, bool HOUT, bool ALN, bool RESLN, int TERMS, bool SUMOUT>
__global__ void __launch_bounds__(512) lgemm_kernel(
    const float* __restrict__ X,
    const half* __restrict__ Whi,
    const half* __restrict__ Wlo,
    const float* __restrict__ bias,
    const float* __restrict__ res,
    const float* __restrict__ statsA,
    const float* __restrict__ statsR,
    float* __restrict__ Y,
    half*  __restrict__ Yh,
    float* __restrict__ acc)
{
    constexpr int BS = (TERMS == 1) ? 432 : 240;
    constexpr int WS = BS / 4;
    constexpr int AHI = 0;
    constexpr int APL = 128 * BS;
    constexpr int ALO = (TERMS == 3) ? APL : 0;
    constexpr int BHI = (TERMS == 3) ? 2 * APL : APL;
    constexpr int BPL = 224 * BS;
    constexpr int BLO = BHI + BPL;

    char* sm = dyn_smem;
    const int row0 = blockIdx.x * 128;
    const int b = blockIdx.x >> 3;
    const float4* X4 = (const float4*)(X + (size_t)row0 * DIM);
    const float4* Whi4 = (const float4*)Whi;
    const float4* Wlo4 = (const float4*)Wlo;
    const int tid = threadIdx.x;
    const int warp = tid >> 5, lane = tid & 31;
    const int gid = lane >> 2, tig = lane & 3;
    const int m0 = (warp & 3) * 32;
    const int n0 = (warp >> 2) * 56;

    float mA = 0.f, rA = 1.f;
    if (ALN) { mA = statsA[2 * b]; rA = statsA[2 * b + 1]; }

    float c[2][7][4];
#pragma unroll
    for (int mt = 0; mt < 2; mt++)
#pragma unroll
        for (int nt = 0; nt < 7; nt++)
#pragma unroll
            for (int q = 0; q < 4; q++) c[mt][nt][q] = 0.f;

    const int NCH = (TERMS == 1) ? 1 : 2;
#pragma unroll
    for (int ch = 0; ch < NCH; ch++) {
        const int kh0 = (TERMS == 1) ? 0 : ch * 112;
        const int kc  = (TERMS == 1) ? 208 : (ch == 0 ? 112 : 96);
        const int G   = kc >> 2;
        const int G2  = kc >> 3;

        for (int idx = tid; idx < 128 * G; idx += 512) {
            int row = idx / G, g = idx - row * G;
            int jg = (kh0 >> 2) + g;
            float4 v = (jg < 50) ? X4[(size_t)row * 50 + jg] : make_float4(0.f, 0.f, 0.f, 0.f);
            if (ALN) {
                v.x = (v.x - mA) * rA; v.y = (v.y - mA) * rA;
                v.z = (v.z - mA) * rA; v.w = (v.w - mA) * rA;
            }
            half hx = __float2half_rn(v.x), hy = __float2half_rn(v.y);
            half hz = __float2half_rn(v.z), hw = __float2half_rn(v.w);
            uint2 hi;
            hi.x = ((uint32_t)__half_as_ushort(hx)) | ((uint32_t)__half_as_ushort(hy) << 16);
            hi.y = ((uint32_t)__half_as_ushort(hz)) | ((uint32_t)__half_as_ushort(hw) << 16);
            *(uint2*)(sm + AHI + row * BS + g * 8) = hi;
            if (TERMS == 3) {
                half lx = __float2half_rn(v.x - __half2float(hx));
                half ly = __float2half_rn(v.y - __half2float(hy));
                half lz = __float2half_rn(v.z - __half2float(hz));
                half lw = __float2half_rn(v.w - __half2float(hw));
                uint2 lo;
                lo.x = ((uint32_t)__half_as_ushort(lx)) | ((uint32_t)__half_as_ushort(ly) << 16);
                lo.y = ((uint32_t)__half_as_ushort(lz)) | ((uint32_t)__half_as_ushort(lw) << 16);
                *(uint2*)(sm + ALO + row * BS + g * 8) = lo;
            }
        }
        for (int idx = tid; idx < 224 * G2; idx += 512) {
            int row = idx / G2, g = idx - row * G2;
            int jg = (kh0 >> 3) + g;
            *(float4*)(sm + BHI + row * BS + g * 16) = Whi4[(size_t)row * 26 + jg];
            if (TERMS == 3)
                *(float4*)(sm + BLO + row * BS + g * 16) = Wlo4[(size_t)row * 26 + jg];
        }
        __syncthreads();

        const uint32_t* Ah = (const uint32_t*)(sm + AHI);
        const uint32_t* Al = (const uint32_t*)(sm + ALO);
        const uint32_t* Bh = (const uint32_t*)(sm + BHI);
        const uint32_t* Bl = (const uint32_t*)(sm + BLO);
        const int nks = kc >> 4;

        for (int ks = 0; ks < nks; ks++) {
            const int kw = ks * 8 + tig;
            uint32_t ahi[2][4], alo[2][4];
#pragma unroll
            for (int mt = 0; mt < 2; mt++) {
                int r = (m0 + mt * 16 + gid) * WS + kw;
                ahi[mt][0] = Ah[r];           ahi[mt][1] = Ah[r + 8 * WS];
                ahi[mt][2] = Ah[r + 4];       ahi[mt][3] = Ah[r + 8 * WS + 4];
                if (TERMS == 3) {
                    alo[mt][0] = Al[r];       alo[mt][1] = Al[r + 8 * WS];
                    alo[mt][2] = Al[r + 4];   alo[mt][3] = Al[r + 8 * WS + 4];
                }
            }
#pragma unroll
            for (int nt = 0; nt < 7; nt++) {
                int r = (n0 + nt * 8 + gid) * WS + kw;
                uint32_t bhi[2] = { Bh[r], Bh[r + 4] };
                if (TERMS == 3) {
                    uint32_t blo[2] = { Bl[r], Bl[r + 4] };
#pragma unroll
                    for (int mt = 0; mt < 2; mt++) {
                        mma_f16(c[mt][nt], ahi[mt], blo);
                        mma_f16(c[mt][nt], alo[mt], bhi);
                        mma_f16(c[mt][nt], ahi[mt], bhi);
                    }
                } else {
#pragma unroll
                    for (int mt = 0; mt < 2; mt++) mma_f16(c[mt][nt], ahi[mt], bhi);
                }
            }
        }
        __syncthreads();
    }

    float mR = 0.f, rR = 1.f;
    if (RESLN) { mR = statsR[2 * b]; rR = statsR[2 * b + 1]; }

    float* Yb = (!HOUT) ? (Y + (size_t)row0 * DIM) : (float*)0;
    half*  Yhb = HOUT ? (Yh + (size_t)row0 * PHS) : (half*)0;
    const float* Rb = ADDRES ? (res + (size_t)row0 * DIM) : (const float*)0;

    float ssum = 0.f, ssq = 0.f;
#pragma unroll
    for (int mt = 0; mt < 2; mt++) {
        int r0 = m0 + mt * 16 + gid;
#pragma unroll
        for (int nt = 0; nt < 7; nt++) {
            int col = n0 + nt * 8 + 2 * tig;
            if (col < DIM) {
                float bx = bias[col], by = bias[col + 1];
                float v0 = c[mt][nt][0] + bx, v1 = c[mt][nt][1] + by;
                float v2 = c[mt][nt][2] + bx, v3 = c[mt][nt][3] + by;
                if (ADDRES) {
                    float q0 = Rb[(size_t)r0 * DIM + col],       q1 = Rb[(size_t)r0 * DIM + col + 1];
                    float q2 = Rb[(size_t)(r0 + 8) * DIM + col], q3 = Rb[(size_t)(r0 + 8) * DIM + col + 1];
                    if (RESLN) {
                        q0 = (q0 - mR) * rR; q1 = (q1 - mR) * rR;
                        q2 = (q2 - mR) * rR; q3 = (q3 - mR) * rR;
                    }
                    v0 += q0; v1 += q1; v2 += q2; v3 += q3;
                }
                if (RELU) {
                    v0 = fmaxf(v0, 0.f); v1 = fmaxf(v1, 0.f);
                    v2 = fmaxf(v2, 0.f); v3 = fmaxf(v3, 0.f);
                }
                if (SUMOUT) {
                    ssum += (v0 + v1) + (v2 + v3);
                    ssq  += v0 * v0 + v1 * v1 + v2 * v2 + v3 * v3;
                }
                if (HOUT) {
                    *(__half2*)(Yhb + (size_t)r0 * PHS + col)       = __floats2half2_rn(v0, v1);
                    *(__half2*)(Yhb + (size_t)(r0 + 8) * PHS + col) = __floats2half2_rn(v2, v3);
                } else {
                    *(float2*)(Yb + (size_t)r0 * DIM + col)       = make_float2(v0, v1);
                    *(float2*)(Yb + (size_t)(r0 + 8) * DIM + col) = make_float2(v2, v3);
                }
            } else if (HOUT && col < PHS) {
                __half2 z = __floats2half2_rn(0.f, 0.f);
                *(__half2*)(Yhb + (size_t)r0 * PHS + col)       = z;
                *(__half2*)(Yhb + (size_t)(r0 + 8) * PHS + col) = z;
            }
        }
    }
    if (SUMOUT) {
        __shared__ float rbuf[32];
#pragma unroll
        for (int off = 16; off; off >>= 1) {
            ssum += __shfl_xor_sync(0xffffffffu, ssum, off);
            ssq  += __shfl_xor_sync(0xffffffffu, ssq,  off);
        }
        if (lane == 0) { rbuf[warp] = ssum; rbuf[16 + warp] = ssq; }
        __syncthreads();
        if (tid == 0) {
            float S = 0.f, S2 = 0.f;
#pragma unroll
            for (int w = 0; w < 16; w++) { S += rbuf[w]; S2 += rbuf[16 + w]; }
            atomicAdd(acc + 2 * b, S);
            atomicAdd(acc + 2 * b + 1, S2);
        }
    }
}

// ====== fused FF: t2 = relu(ln(t)@W1+b1)@W2 + b2 + ln(t), ln-sums fused ======
// 512 threads. Phase1: 1-term fp16 GEMM (K=208). ff1 -> smem hi/lo planes.
// Phase2: 3-term fp16 GEMM over ff1 (K=208 in 2 chunks), W2 planes restaged/chunk.
#define FF_HI   0
#define FF_LO   55296                         /* 128*432 */
#define FF_B2   110592                        /* 2*128*432 */
#define FF_B2LO (110592 + 53760)              /* + 224*240 */
#define FF_SMEM (110592 + 2 * 53760)          /* 218112 */

__global__ void __launch_bounds__(512) ffgemm_kernel(
    const float* __restrict__ T,          // trunk (pre-LN)
    const half* __restrict__ W1hi,
    const half* __restrict__ W2hi,
    const half* __restrict__ W2lo,
    const float* __restrict__ b1,
    const float* __restrict__ b2,
    const float* __restrict__ stats,      // LN stats for t (A and residual)
    float* __restrict__ Y,                // output trunk
    float* __restrict__ acc)
{
    char* sm = dyn_smem;
    const int row0 = blockIdx.x * 128;
    const int b = blockIdx.x >> 3;
    const float4* T4 = (const float4*)(T + (size_t)row0 * DIM);
    const float4* W1h4 = (const float4*)W1hi;
    const float4* W2h4 = (const float4*)W2hi;
    const float4* W2l4 = (const float4*)W2lo;
    const int tid = threadIdx.x;
    const int warp = tid >> 5, lane = tid & 31;
    const int gid = lane >> 2, tig = lane & 3;
    const int m0 = (warp & 3) * 32;
    const int n0 = (warp >> 2) * 56;

    const float mA = stats[2 * b], rA = stats[2 * b + 1];

    // ---------- phase 1: ff1 = relu(ln(t) @ W1 + b1), 1-term, K=208 ----------
    float c1[2][7][4];
#pragma unroll
    for (int mt = 0; mt < 2; mt++)
#pragma unroll
        for (int nt = 0; nt < 7; nt++)
#pragma unroll
            for (int q = 0; q < 4; q++) c1[mt][nt][q] = 0.f;

    // stage A = ln(t) hi at FF_HI [128][432B]
    for (int idx = tid; idx < 128 * 52; idx += 512) {
        int row = idx / 52, g = idx - row * 52;
        float4 v = (g < 50) ? T4[(size_t)row * 50 + g] : make_float4(0.f, 0.f, 0.f, 0.f);
        v.x = (v.x - mA) * rA; v.y = (v.y - mA) * rA;
        v.z = (v.z - mA) * rA; v.w = (v.w - mA) * rA;
        uint2 hi;
        hi.x = ((uint32_t)__half_as_ushort(__float2half_rn(v.x))) |
               ((uint32_t)__half_as_ushort(__float2half_rn(v.y)) << 16);
        hi.y = ((uint32_t)__half_as_ushort(__float2half_rn(v.z))) |
               ((uint32_t)__half_as_ushort(__float2half_rn(v.w)) << 16);
        *(uint2*)(sm + FF_HI + row * 432 + g * 8) = hi;
    }
    // stage B1 = W1hi full-K at offset FF_LO [224][432B]
    for (int idx = tid; idx < 224 * 26; idx += 512) {
        int row = idx / 26, g = idx - row * 26;
        *(float4*)(sm + FF_LO + row * 432 + g * 16) = W1h4[(size_t)row * 26 + g];
    }
    __syncthreads();
    {
        const uint32_t* Ah = (const uint32_t*)(sm + FF_HI);
        const uint32_t* Bh = (const uint32_t*)(sm + FF_LO);
        for (int ks = 0; ks < 13; ks++) {
            const int kw = ks * 8 + tig;
            uint32_t ahi[2][4];
#pragma unroll
            for (int mt = 0; mt < 2; mt++) {
                int r = (m0 + mt * 16 + gid) * 108 + kw;
                ahi[mt][0] = Ah[r];     ahi[mt][1] = Ah[r + 8 * 108];
                ahi[mt][2] = Ah[r + 4]; ahi[mt][3] = Ah[r + 8 * 108 + 4];
            }
#pragma unroll
            for (int nt = 0; nt < 7; nt++) {
                int r = (n0 + nt * 8 + gid) * 108 + kw;
                uint32_t bhi[2] = { Bh[r], Bh[r + 4] };
#pragma unroll
                for (int mt = 0; mt < 2; mt++) mma_f16(c1[mt][nt], ahi[mt], bhi);
            }
        }
    }
    __syncthreads();   // all reads of FF_HI/FF_LO done

    // ---------- phase 1.5: write ff1 (bias+relu, hi/lo split) into FF_HI/FF_LO ----------
#pragma unroll
    for (int mt = 0; mt < 2; mt++) {
        int r0 = m0 + mt * 16 + gid;
#pragma unroll
        for (int nt = 0; nt < 7; nt++) {
            int col = n0 + nt * 8 + 2 * tig;
            if (col < DIM) {
                float bx = b1[col], by = b1[col + 1];
                float v0 = fmaxf(c1[mt][nt][0] + bx, 0.f);
                float v1 = fmaxf(c1[mt][nt][1] + by, 0.f);
                float v2 = fmaxf(c1[mt][nt][2] + bx, 0.f);
                float v3 = fmaxf(c1[mt][nt][3] + by, 0.f);
                half h0 = __float2half_rn(v0), h1 = __float2half_rn(v1);
                half h2 = __float2half_rn(v2), h3 = __float2half_rn(v3);
                *(uint32_t*)(sm + FF_HI + (size_t)r0 * 432 + col * 2) =
                    ((uint32_t)__half_as_ushort(h0)) | ((uint32_t)__half_as_ushort(h1) << 16);
                *(uint32_t*)(sm + FF_HI + (size_t)(r0 + 8) * 432 + col * 2) =
                    ((uint32_t)__half_as_ushort(h2)) | ((uint32_t)__half_as_ushort(h3) << 16);
                *(uint32_t*)(sm + FF_LO + (size_t)r0 * 432 + col * 2) =
                    pack_h2(v0 - __half2float(h0), v1 - __half2float(h1));
                *(uint32_t*)(sm + FF_LO + (size_t)(r0 + 8) * 432 + col * 2) =
                    pack_h2(v2 - __half2float(h2), v3 - __half2float(h3));
            } else if (col < 208) {
                *(uint32_t*)(sm + FF_HI + (size_t)r0 * 432 + col * 2) = 0u;
                *(uint32_t*)(sm + FF_HI + (size_t)(r0 + 8) * 432 + col * 2) = 0u;
                *(uint32_t*)(sm + FF_LO + (size_t)r0 * 432 + col * 2) = 0u;
                *(uint32_t*)(sm + FF_LO + (size_t)(r0 + 8) * 432 + col * 2) = 0u;
            }
        }
    }

    // ---------- phase 2: t2 = ff1 @ W2 (3-term), 2 K-chunks ----------
    float c2[2][7][4];
#pragma unroll
    for (int mt = 0; mt < 2; mt++)
#pragma unroll
        for (int nt = 0; nt < 7; nt++)
#pragma unroll
            for (int q = 0; q < 4; q++) c2[mt][nt][q] = 0.f;

    for (int ch = 0; ch < 2; ch++) {
        const int kh0 = ch * 112;
        const int kc  = (ch == 0) ? 112 : 96;
        const int G2  = kc >> 3;
        // stage W2 chunk planes at FF_B2
        for (int idx = tid; idx < 224 * G2; idx += 512) {
            int row = idx / G2, g = idx - row * G2;
            int jg = (kh0 >> 3) + g;
            *(float4*)(sm + FF_B2   + row * 240 + g * 16) = W2h4[(size_t)row * 26 + jg];
            *(float4*)(sm + FF_B2LO + row * 240 + g * 16) = W2l4[(size_t)row * 26 + jg];
        }
        __syncthreads();

        const uint32_t* Ah = (const uint32_t*)(sm + FF_HI);
        const uint32_t* Al = (const uint32_t*)(sm + FF_LO);
        const uint32_t* Bh = (const uint32_t*)(sm + FF_B2);
        const uint32_t* Bl = (const uint32_t*)(sm + FF_B2LO);
        const int nks = kc >> 4;
        const int kwb = ch * 56;

        for (int ks = 0; ks < nks; ks++) {
            const int kw = kwb + ks * 8 + tig;
            const int kwB = ks * 8 + tig;
            uint32_t ahi[2][4], alo[2][4];
#pragma unroll
            for (int mt = 0; mt < 2; mt++) {
                int r = (m0 + mt * 16 + gid) * 108 + kw;
                ahi[mt][0] = Ah[r];     ahi[mt][1] = Ah[r + 8 * 108];
                ahi[mt][2] = Ah[r + 4]; ahi[mt][3] = Ah[r + 8 * 108 + 4];
                alo[mt][0] = Al[r];     alo[mt][1] = Al[r + 8 * 108];
                alo[mt][2] = Al[r + 4]; alo[mt][3] = Al[r + 8 * 108 + 4];
            }
#pragma unroll
            for (int nt = 0; nt < 7; nt++) {
                int r = (n0 + nt * 8 + gid) * 60 + kwB;
                uint32_t bhi[2] = { Bh[r], Bh[r + 4] };
                uint32_t blo[2] = { Bl[r], Bl[r + 4] };
#pragma unroll
                for (int mt = 0; mt < 2; mt++) {
                    mma_f16(c2[mt][nt], ahi[mt], blo);
                    mma_f16(c2[mt][nt], alo[mt], bhi);
                    mma_f16(c2[mt][nt], ahi[mt], bhi);
                }
            }
        }
        __syncthreads();
    }

    // ---------- epilogue: + b2 + ln(t), ln-sums ----------
    float* Yb = Y + (size_t)row0 * DIM;
    const float* Rb = T + (size_t)row0 * DIM;
    float ssum = 0.f, ssq = 0.f;
#pragma unroll
    for (int mt = 0; mt < 2; mt++) {
        int r0 = m0 + mt * 16 + gid;
#pragma unroll
        for (int nt = 0; nt < 7; nt++) {
            int col = n0 + nt * 8 + 2 * tig;
            if (col < DIM) {
                float bx = b2[col], by = b2[col + 1];
                float v0 = c2[mt][nt][0] + bx, v1 = c2[mt][nt][1] + by;
                float v2 = c2[mt][nt][2] + bx, v3 = c2[mt][nt][3] + by;
                float q0 = (Rb[(size_t)r0 * DIM + col] - mA) * rA;
                float q1 = (Rb[(size_t)r0 * DIM + col + 1] - mA) * rA;
                float q2 = (Rb[(size_t)(r0 + 8) * DIM + col] - mA) * rA;
                float q3 = (Rb[(size_t)(r0 + 8) * DIM + col + 1] - mA) * rA;
                v0 += q0; v1 += q1; v2 += q2; v3 += q3;
                ssum += (v0 + v1) + (v2 + v3);
                ssq  += v0 * v0 + v1 * v1 + v2 * v2 + v3 * v3;
                *(float2*)(Yb + (size_t)r0 * DIM + col)       = make_float2(v0, v1);
                *(float2*)(Yb + (size_t)(r0 + 8) * DIM + col) = make_float2(v2, v3);
            }
        }
    }
    {
        __shared__ float rbuf[32];
#pragma unroll
        for (int off = 16; off; off >>= 1) {
            ssum += __shfl_xor_sync(0xffffffffu, ssum, off);
            ssq  += __shfl_xor_sync(0xffffffffu, ssq,  off);
        }
        if (lane == 0) { rbuf[warp] = ssum; rbuf[16 + warp] = ssq; }
        __syncthreads();
        if (tid == 0) {
            float S = 0.f, S2 = 0.f;
#pragma unroll
            for (int w = 0; w < 16; w++) { S += rbuf[w]; S2 += rbuf[16 + w]; }
            atomicAdd(acc + 2 * b, S);
            atomicAdd(acc + 2 * b + 1, S2);
        }
    }
}

// ===== fused flash attention (R12 version): single K/V tile, ldmatrix.trans V frags =====
#define FA_ROWB 432
#define FA_BUF  (128 * FA_ROWB)
#define FA_SMEM (2 * FA_BUF)

__global__ void __launch_bounds__(256, 1) fattn_kernel(const half* __restrict__ Ph,
                                                       float* __restrict__ C) {
    char* smem = dyn_smem;
    const uint32_t sb = smem_u32(smem);
    const int b = blockIdx.y, s0 = blockIdx.x * 128;
    const int tid = threadIdx.x, warp = tid >> 5, lane = tid & 31;
    const int gid = lane >> 2, tig = lane & 3;
    const int m0 = warp * 16;

    const char* PhB = (const char*)(Ph + (size_t)b * SEQ * PHS);

    auto stage = [&](int ch, int buf) {
        uint32_t kbase = sb + buf * FA_BUF;
        const char* ksrc = PhB + (size_t)(ch * 128) * 416;
        for (int i = tid; i < 128 * 26; i += 256) {
            int r = i / 26, c4 = i - r * 26;
            cp16(kbase + r * FA_ROWB + c4 * 16, ksrc + (size_t)r * 416 + c4 * 16);
        }
    };

    uint32_t qf[13][4];
    {
        const uint32_t* q0 = (const uint32_t*)(PhB + (size_t)(s0 + m0 + gid) * 416);
        const uint32_t* q8 = (const uint32_t*)(PhB + (size_t)(s0 + m0 + gid + 8) * 416);
#pragma unroll
        for (int ks = 0; ks < 13; ks++) {
            qf[ks][0] = q0[ks * 8 + tig];
            qf[ks][1] = q8[ks * 8 + tig];
            qf[ks][2] = q0[ks * 8 + tig + 4];
            qf[ks][3] = q8[ks * 8 + tig + 4];
        }
    }

    const uint32_t lbase = (uint32_t)(((lane >> 3) & 1) * 8 * FA_ROWB
                                      + (lane & 7) * FA_ROWB
                                      + ((lane >> 4) & 1) * 16);

    float o[25][4];
#pragma unroll
    for (int nt = 0; nt < 25; nt++)
#pragma unroll
        for (int q = 0; q < 4; q++) o[nt][q] = 0.f;
    float z0 = 0.f, z8 = 0.f;

    stage(0, 0);
    CP_COMMIT();

    for (int ch = 0; ch < 8; ch++) {
        const int buf = ch & 1;
        CP_WAIT0();
        __syncthreads();
        if (ch < 7) { stage(ch + 1, buf ^ 1); CP_COMMIT(); }

        const uint32_t kb = sb + buf * FA_BUF;
        const uint32_t* Kh = (const uint32_t*)(smem + buf * FA_BUF);

        uint32_t afr[8][4];
        const float inv = 0.07071067811865475f;
#pragma unroll
        for (int kt = 0; kt < 8; kt++) {
            float sa[4] = {0.f, 0.f, 0.f, 0.f};
            float sc[4] = {0.f, 0.f, 0.f, 0.f};
            const uint32_t* k0p = Kh + (kt * 16 + gid) * 108 + tig;
            const uint32_t* k1p = k0p + 8 * 108;
#pragma unroll
            for (int ks = 0; ks < 13; ks++) {
                uint32_t b0[2] = { k0p[ks * 8], k0p[ks * 8 + 4] };
                mma_f16(sa, qf[ks], b0);
                uint32_t b1[2] = { k1p[ks * 8], k1p[ks * 8 + 4] };
                mma_f16(sc, qf[ks], b1);
            }
            float e0 = __expf(fmaf(sa[0], inv, -8.f));
            float e1 = __expf(fmaf(sa[1], inv, -8.f));
            float e2 = __expf(fmaf(sa[2], inv, -8.f));
            float e3 = __expf(fmaf(sa[3], inv, -8.f));
            float f0 = __expf(fmaf(sc[0], inv, -8.f));
            float f1 = __expf(fmaf(sc[1], inv, -8.f));
            float f2 = __expf(fmaf(sc[2], inv, -8.f));
            float f3 = __expf(fmaf(sc[3], inv, -8.f));
            z0 += (e0 + e1) + (f0 + f1);
            z8 += (e2 + e3) + (f2 + f3);
            afr[kt][0] = pack_h2(e0, e1);
            afr[kt][1] = pack_h2(e2, e3);
            afr[kt][2] = pack_h2(f0, f1);
            afr[kt][3] = pack_h2(f2, f3);
        }
#pragma unroll
        for (int ntp = 0; ntp < 13; ntp++) {
#pragma unroll
            for (int kt = 0; kt < 8; kt++) {
                uint32_t r0, r1, r2, r3;
                ldsm_x4_t(r0, r1, r2, r3, kb + lbase + kt * (16 * FA_ROWB) + ntp * 32);
                uint32_t bA[2] = { r0, r1 };
                mma_f16(o[2 * ntp], afr[kt], bA);
                if (ntp < 12) {
                    uint32_t bB[2] = { r2, r3 };
                    mma_f16(o[2 * ntp + 1], afr[kt], bB);
                }
            }
        }
    }

    z0 += __shfl_xor_sync(0xffffffffu, z0, 1);
    z0 += __shfl_xor_sync(0xffffffffu, z0, 2);
    z8 += __shfl_xor_sync(0xffffffffu, z8, 1);
    z8 += __shfl_xor_sync(0xffffffffu, z8, 2);
    float rz0 = 1.f / z0, rz8 = 1.f / z8;

    float* Cb  = C + ((size_t)b * SEQ + s0 + m0 + gid) * DIM;
    float* Cb8 = Cb + 8 * DIM;
#pragma unroll
    for (int nt = 0; nt < 25; nt++) {
        int col = nt * 8 + 2 * tig;
        *(float2*)(Cb  + col) = make_float2(o[nt][0] * rz0, o[nt][1] * rz0);
        *(float2*)(Cb8 + col) = make_float2(o[nt][2] * rz8, o[nt][3] * rz8);
    }
}

// ================= final classifier =================
__global__ void final_kernel(const float* __restrict__ t, const float* __restrict__ stats,
                             const float* __restrict__ Wd, const float* __restrict__ bd,
                             float* __restrict__ out) {
    int b = blockIdx.x;
    int c = threadIdx.x;
    float m = stats[2 * b], rs = stats[2 * b + 1];
    const float* row = t + ((size_t)b * SEQ + (SEQ - 1)) * DIM;
    if (c < NCLS) {
        float acc = bd[c];
        for (int d = 0; d < DIM; d++)
            acc += (row[d] - m) * rs * Wd[d * NCLS + c];
        out[b * NCLS + c] = acc;
    }
}

// ================= host launcher =================
extern "C" void kernel_launch(void* const* d_in, const int* in_sizes, int n_in,
                              void* d_out, int out_size) {
    (void)in_sizes; (void)n_in; (void)out_size;
    const int*   x    = (const int*)  d_in[0];
    const float* emb  = (const float*)d_in[1];
    const float* pos  = (const float*)d_in[2];
    const float* Wp   = (const float*)d_in[3];
    const float* bp   = (const float*)d_in[4];
    const float* Wm   = (const float*)d_in[5];
    const float* bm   = (const float*)d_in[6];
    const float* W1   = (const float*)d_in[7];
    const float* b1   = (const float*)d_in[8];
    const float* W2   = (const float*)d_in[9];
    const float* b2   = (const float*)d_in[10];
    const float* Wd   = (const float*)d_in[11];
    const float* bd   = (const float*)d_in[12];
    float* out = (float*)d_out;

    float *h_, *t_, *c_, *st_, *ac_;
    half *Ph_, *Whi_, *Wlo_;
    cudaGetSymbolAddress((void**)&h_,   g_h);
    cudaGetSymbolAddress((void**)&t_,   g_t);
    cudaGetSymbolAddress((void**)&c_,   g_c);
    cudaGetSymbolAddress((void**)&Ph_,  g_Ph);
    cudaGetSymbolAddress((void**)&Whi_, g_Whi);
    cudaGetSymbolAddress((void**)&Wlo_, g_Wlo);
    cudaGetSymbolAddress((void**)&st_,  g_stats);
    cudaGetSymbolAddress((void**)&ac_,  g_acc);

    const half* WpHi = Whi_;                  const half* WpLo = Wlo_;
    const half* WeHi = Whi_ + 1 * NPAD * KH;  const half* WeLo = Wlo_ + 1 * NPAD * KH;
    const half* W1Hi = Whi_ + 2 * NPAD * KH;
    const half* W2Hi = Whi_ + 3 * NPAD * KH;  const half* W2Lo = Wlo_ + 3 * NPAD * KH;
    float* st1 = st_;
    float* st2 = st_ + 2 * BATCH;
    float* ac1 = ac_;
    float* ac2 = ac_ + 2 * BATCH;

    const int SM_LG1 = 128 * 432 + 224 * 432;              // 152064 (TERMS=1)
    const int SM_LG3 = 2 * 128 * 240 + 2 * 224 * 240;      // 168960 (TERMS=3)

    // RELU, ADDRES, HOUT, ALN, RESLN, TERMS, SUMOUT
    auto L_proj0 = lgemm_kernel<false, false, true,  false, false, 1, false>;
    auto L_proj1 = lgemm_kernel<false, false, true,  true,  false, 1, false>;
    auto L_wm0   = lgemm_kernel<false, true,  false, false, false, 3, true >;
    auto L_res3  = lgemm_kernel<false, true,  false, false, true,  3, true >;
    cudaFuncSetAttribute(L_proj0, cudaFuncAttributeMaxDynamicSharedMemorySize, SM_LG1);
    cudaFuncSetAttribute(L_proj1, cudaFuncAttributeMaxDynamicSharedMemorySize, SM_LG1);
    cudaFuncSetAttribute(L_wm0,   cudaFuncAttributeMaxDynamicSharedMemorySize, SM_LG3);
    cudaFuncSetAttribute(L_res3,  cudaFuncAttributeMaxDynamicSharedMemorySize, SM_LG3);
    cudaFuncSetAttribute(ffgemm_kernel, cudaFuncAttributeMaxDynamicSharedMemorySize, FF_SMEM);
    cudaFuncSetAttribute(fattn_kernel, cudaFuncAttributeMaxDynamicSharedMemorySize, FA_SMEM);

    const int LGRID = BATCH * SEQ / 128;             // 512
    const int ELT4  = BATCH * SEQ * DIM / 4;

    wprep_kernel<<<dim3((NPAD * KH + 255) / 256, 4), 256>>>(Wp, Wm, W1, W2, Whi_, Wlo_);
    embed_kernel<<<(ELT4 + 255) / 256, 256>>>(x, (const float4*)emb, (const float4*)pos, (float4*)h_);

    for (int st = 0; st < 2; st++) {
        // p = fp16(lnA?(h) @ Wp + bp) -> Ph
        if (st == 0)
            L_proj0<<<LGRID, 512, SM_LG1>>>(h_, WpHi, WpLo, bp, nullptr, nullptr, nullptr, nullptr, Ph_, nullptr);
        else
            L_proj1<<<LGRID, 512, SM_LG1>>>(h_, WpHi, WpLo, bp, nullptr, st2, nullptr, nullptr, Ph_, nullptr);
        // fused attention: c = softmax(P P^T / sqrt(200)) @ P
        fattn_kernel<<<dim3(SEQ / 128, BATCH), 256, FA_SMEM>>>(Ph_, c_);
        // t = c @ WmEff + bm + lnR?(h)   (3-term fp16 trunk, ln-sums fused)
        if (st == 0)
            L_wm0<<<LGRID, 512, SM_LG3>>>(c_, WeHi, WeLo, bm, h_, nullptr, nullptr, t_, nullptr, ac1);
        else
            L_res3<<<LGRID, 512, SM_LG3>>>(c_, WeHi, WeLo, bm, h_, nullptr, st2, t_, nullptr, ac1);
        finalize_kernel<<<1, 64>>>(ac1, st1);
        // fused FF: t2 = relu(ln(t)@W1+b1)@W2 + b2 + ln(t) -> h_, ln-sums -> ac2
        ffgemm_kernel<<<LGRID, 512, FF_SMEM>>>(t_, W1Hi, W2Hi, W2Lo, b1, b2, st1, h_, ac2);
        finalize_kernel<<<1, 64>>>(ac2, st2);
    }
    final_kernel<<<BATCH, 32>>>(h_, st2, Wd, bd, out);
}